// round 1
// baseline (speedup 1.0000x reference)
#include <cuda_runtime.h>
#include <math.h>

#define N_NODES 100000
#define N_EDGES 1600000
#define H 64

// Scratch (device globals — no allocation allowed)
__device__ float g_deg[N_NODES];
__device__ float g_dinv[N_NODES];
__device__ float g_y[(size_t)N_NODES * H];   // x @ W for current layer
__device__ float g_a[(size_t)N_NODES * H];   // layer-1 output
__device__ float g_b2[(size_t)N_NODES * H];  // layer-2 output

__global__ void init_deg_kernel() {
    int i = blockIdx.x * blockDim.x + threadIdx.x;
    if (i < N_NODES) g_deg[i] = 1.0f;  // +1 self-loop
}

__global__ void count_deg_kernel(const int* __restrict__ ei) {
    int e = blockIdx.x * blockDim.x + threadIdx.x;
    if (e < N_EDGES) atomicAdd(&g_deg[ei[N_EDGES + e]], 1.0f);
}

__global__ void dinv_kernel() {
    int i = blockIdx.x * blockDim.x + threadIdx.x;
    if (i < N_NODES) g_dinv[i] = rsqrtf(g_deg[i]);
}

// y = x @ W ; out = y * dinv(row)^2 + b   (scatter-add target init)
// xsel: 0=ext (embeddings), 1=g_a, 2=g_b2 ; osel: 0=ext (d_out), 1=g_a, 2=g_b2
__global__ void __launch_bounds__(256) gemm_kernel(
    const float* __restrict__ x_ext, const float* __restrict__ W,
    const float* __restrict__ bias, float* __restrict__ out_ext,
    int xsel, int osel)
{
    __shared__ float4 Ws[64][16];  // W row-major [k][c], as float4 along c
    __shared__ float4 bs[16];

    const float* x = (xsel == 0) ? x_ext : (xsel == 1 ? g_a : g_b2);
    float* out = (osel == 0) ? out_ext : (osel == 1 ? g_a : g_b2);

    int tid = threadIdx.x;
    for (int i = tid; i < 64 * 16; i += 256)
        ((float4*)Ws)[i] = ((const float4*)W)[i];
    if (tid < 16) bs[tid] = ((const float4*)bias)[tid];
    __syncthreads();

    int row = blockIdx.x * 256 + tid;
    if (row >= N_NODES) return;

    const float4* x4 = (const float4*)x + (size_t)row * 16;

    float4 acc[16];
#pragma unroll
    for (int c = 0; c < 16; c++) acc[c] = make_float4(0.f, 0.f, 0.f, 0.f);

#pragma unroll 4
    for (int k4 = 0; k4 < 16; k4++) {
        float4 xv = x4[k4];
        float xs[4];
        xs[0] = xv.x; xs[1] = xv.y; xs[2] = xv.z; xs[3] = xv.w;
#pragma unroll
        for (int j = 0; j < 4; j++) {
            float xk = xs[j];
            int k = k4 * 4 + j;
#pragma unroll
            for (int c = 0; c < 16; c++) {
                float4 w = Ws[k][c];
                acc[c].x = fmaf(xk, w.x, acc[c].x);
                acc[c].y = fmaf(xk, w.y, acc[c].y);
                acc[c].z = fmaf(xk, w.z, acc[c].z);
                acc[c].w = fmaf(xk, w.w, acc[c].w);
            }
        }
    }

    float di = g_dinv[row];
    float s = di * di;
    float4* y4 = (float4*)g_y + (size_t)row * 16;
    float4* o4 = (float4*)out + (size_t)row * 16;
#pragma unroll
    for (int c = 0; c < 16; c++) {
        y4[c] = acc[c];
        float4 bv = bs[c];
        float4 o;
        o.x = fmaf(acc[c].x, s, bv.x);
        o.y = fmaf(acc[c].y, s, bv.y);
        o.z = fmaf(acc[c].z, s, bv.z);
        o.w = fmaf(acc[c].w, s, bv.w);
        o4[c] = o;
    }
}

// For each edge: out[dst] += y[src] * dinv[src] * dinv[dst]
// 16 threads per edge, one red.global.add.v4.f32 (16B) each.
__global__ void __launch_bounds__(256) edge_kernel(
    const int* __restrict__ ei, float* __restrict__ out_ext, int osel)
{
    float* out = (osel == 0) ? out_ext : (osel == 1 ? g_a : g_b2);

    unsigned tid = blockIdx.x * 256u + threadIdx.x;
    unsigned e = tid >> 4;
    if (e >= N_EDGES) return;
    unsigned q = tid & 15u;

    int s = ei[e];
    int d = ei[N_EDGES + e];
    float norm = g_dinv[s] * g_dinv[d];

    float4 v = ((const float4*)g_y)[(size_t)s * 16 + q];
    v.x *= norm; v.y *= norm; v.z *= norm; v.w *= norm;

    float* addr = out + (size_t)d * 64 + q * 4;
    asm volatile("red.global.add.v4.f32 [%0], {%1,%2,%3,%4};"
                 :: "l"(addr), "f"(v.x), "f"(v.y), "f"(v.z), "f"(v.w)
                 : "memory");
}

extern "C" void kernel_launch(void* const* d_in, const int* in_sizes, int n_in,
                              void* d_out, int out_size)
{
    const float* emb = (const float*)d_in[0];
    const int*   ei  = (const int*)d_in[1];
    const float* W1  = (const float*)d_in[2];
    const float* b1  = (const float*)d_in[3];
    const float* W2  = (const float*)d_in[4];
    const float* b2  = (const float*)d_in[5];
    const float* W3  = (const float*)d_in[6];
    const float* b3  = (const float*)d_in[7];
    float* out = (float*)d_out;

    const int node_blocks = (N_NODES + 255) / 256;
    const int edge_blocks = (N_EDGES + 255) / 256;
    const int ework_blocks = (N_EDGES * 16 + 255) / 256;  // 100000

    // Degree + dinv (once; shared by all 3 layers)
    init_deg_kernel<<<node_blocks, 256>>>();
    count_deg_kernel<<<edge_blocks, 256>>>(ei);
    dinv_kernel<<<node_blocks, 256>>>();

    // Layer 1: x=emb -> g_a
    gemm_kernel<<<node_blocks, 256>>>(emb, W1, b1, out, /*xsel=*/0, /*osel=*/1);
    edge_kernel<<<ework_blocks, 256>>>(ei, out, /*osel=*/1);

    // Layer 2: x=g_a -> g_b2
    gemm_kernel<<<node_blocks, 256>>>(emb, W2, b2, out, /*xsel=*/1, /*osel=*/2);
    edge_kernel<<<ework_blocks, 256>>>(ei, out, /*osel=*/2);

    // Layer 3: x=g_b2 -> d_out
    gemm_kernel<<<node_blocks, 256>>>(emb, W3, b3, out, /*xsel=*/2, /*osel=*/0);
    edge_kernel<<<ework_blocks, 256>>>(ei, out, /*osel=*/0);
}